// round 16
// baseline (speedup 1.0000x reference)
#include <cuda_runtime.h>
#include <cuda_bf16.h>

#define NT   256
#define NBLK 740      // exactly one wave: 5 CTAs/SM x 148 SMs
#define MAXU 16384    // max work units (unit size auto-scales if exceeded)

// Scratch. Unit partials: every slot in [0, NU) written every launch.
// Counters reset by the last block -> graph-replay deterministic.
__device__ float g_unit_partials[MAXU];
__device__ float g_rowsums[128];
__device__ int   g_ticket = 0;
__device__ int   g_count  = 0;

// 128-bit read-only load with 256B L2 fetch-granularity hint: halves the
// number of DRAM/LTS requests per byte if the cap is request-rate-bound.
__device__ __forceinline__ float4 ldg256(const float4* p) {
    float4 v;
    asm("ld.global.nc.L2::256B.v4.f32 {%0,%1,%2,%3}, [%4];"
        : "=f"(v.x), "=f"(v.y), "=f"(v.z), "=f"(v.w) : "l"(p));
    return v;
}

__device__ __forceinline__ float block_reduce(float v, float* sdata) {
    int tid = threadIdx.x;
    #pragma unroll
    for (int off = 16; off > 0; off >>= 1)
        v += __shfl_down_sync(0xFFFFFFFFu, v, off);
    if ((tid & 31) == 0) sdata[tid >> 5] = v;
    __syncthreads();
    float r = 0.0f;
    if (tid < (NT / 32)) r = sdata[tid];
    if (tid < 32) {
        #pragma unroll
        for (int off = (NT / 64); off > 0; off >>= 1)
            r += __shfl_down_sync(0xFFFFFFFFu, r, off);
    }
    return r;  // valid in tid 0
}

__device__ __forceinline__ float sq4(float4 v, float s) {
    s = fmaf(v.x, v.x, s); s = fmaf(v.y, v.y, s);
    s = fmaf(v.z, v.z, s); s = fmaf(v.w, v.w, s);
    return s;
}

// Unit boundaries: tensor t owns units [ub[t], ub[t+1]); NU = ub[7].
__global__ __launch_bounds__(NT, 5)
void wr_fused_kernel(const float* __restrict__ wq, const float* __restrict__ wk,
                     const float* __restrict__ wv, const float* __restrict__ wo,
                     const float* __restrict__ w1, const float* __restrict__ w2,
                     const float* __restrict__ embed, const float* __restrict__ biases,
                     long n0, long n1, long n2, long n3, long n4, long n5, long n6,
                     int u1, int u2, int u3, int u4, int u5, int u6, int u7,
                     int unit_f4,
                     float* __restrict__ out)
{
    __shared__ float sdata[NT / 32];
    __shared__ int   s_u;
    const float* ptrs[7] = {wq, wk, wv, wo, w1, w2, embed};
    const long ns[7]     = {n0, n1, n2, n3, n4, n5, n6};
    const int  ub[8]     = {0, u1, u2, u3, u4, u5, u6, u7};
    const int  NU        = u7;
    const int  tid       = threadIdx.x;
    const int  bid       = blockIdx.x;

    // ---- dynamic work-stealing over fixed 32KB units ----
    if (tid == 0) s_u = atomicAdd(&g_ticket, 1);
    __syncthreads();
    int u = s_u;
    while (u < NU) {
        int t = 0;
        #pragma unroll
        for (int k = 1; k < 7; k++) if (u >= ub[k]) t = k;
        const float4* __restrict__ p = (const float4*)ptrs[t];
        const long n4e = ns[t] >> 2;
        const long lo  = (long)(u - ub[t]) * unit_f4;
        long hi = lo + unit_f4; if (hi > n4e) hi = n4e;

        float s0 = 0.f, s1 = 0.f, s2 = 0.f, s3 = 0.f;
        float s4 = 0.f, s5 = 0.f, s6 = 0.f, s7 = 0.f;
        long i = lo + tid;
        for (; i + 7 * NT < hi; i += 8 * NT) {
            float4 a = ldg256(p + i);
            float4 b = ldg256(p + i + NT);
            float4 c = ldg256(p + i + 2 * NT);
            float4 d = ldg256(p + i + 3 * NT);
            float4 e = ldg256(p + i + 4 * NT);
            float4 f = ldg256(p + i + 5 * NT);
            float4 g = ldg256(p + i + 6 * NT);
            float4 h = ldg256(p + i + 7 * NT);
            s0 = sq4(a, s0); s1 = sq4(b, s1); s2 = sq4(c, s2); s3 = sq4(d, s3);
            s4 = sq4(e, s4); s5 = sq4(f, s5); s6 = sq4(g, s6); s7 = sq4(h, s7);
        }
        for (; i < hi; i += NT) s0 = sq4(ldg256(p + i), s0);

        __syncthreads();  // all threads consumed s_u
        if (tid == 0) s_u = atomicAdd(&g_ticket, 1);  // latency overlaps reduce

        float s = ((s0 + s1) + (s2 + s3)) + ((s4 + s5) + (s6 + s7));
        float r = block_reduce(s, sdata);
        if (tid == 0) g_unit_partials[u] = r;
        __syncthreads();
        u = s_u;
    }

    // Bias rows: blocks 0..127 each do one 8KB row
    if (bid < 128) {
        const float4* __restrict__ pb = (const float4*)(biases) + (long)bid * 512;
        float sb = 0.0f;
        for (int j = tid; j < 512; j += NT) sb = sq4(ldg256(pb + j), sb);
        float rb = block_reduce(sb, sdata);
        if (tid == 0) g_rowsums[bid] = rb;
        __syncthreads();
    }

    // ---- last-block finalize (unit partials are L2-hot) ----
    __shared__ bool is_last;
    __threadfence();
    if (tid == 0) {
        int c = atomicAdd(&g_count, 1);
        is_last = (c == (int)gridDim.x - 1);
    }
    __syncthreads();
    if (!is_last) return;
    __threadfence();  // acquire side

    __shared__ float s_total;
    if (tid == 0) s_total = 0.0f;
    __syncthreads();

    #pragma unroll 1
    for (int tt = 0; tt < 7; tt++) {
        float sv = 0.0f;
        #pragma unroll 4
        for (int j = ub[tt] + tid; j < ub[tt + 1]; j += NT) sv += g_unit_partials[j];
        // scalar tail (n % 4): empty for these shapes
        if (tid == 0) {
            const float* pf = ptrs[tt];
            const long n = ns[tt];
            for (long j = (n >> 2) << 2; j < n; j++) sv = fmaf(pf[j], pf[j], sv);
        }
        float rv = block_reduce(sv, sdata);
        if (tid == 0) s_total += sqrtf(rv);
        __syncthreads();
    }

    float s2v = 0.0f;
    for (int j = tid; j < 128; j += NT) s2v += sqrtf(g_rowsums[j]);
    float rb2 = block_reduce(s2v, sdata);
    if (tid == 0) {
        out[0] = 0.0001f * ((s_total + rb2) / 135.0f);  // 7 mats + 128 rows
        g_ticket = 0;  // reset for next graph replay
        g_count  = 0;
    }
}

extern "C" void kernel_launch(void* const* d_in, const int* in_sizes, int n_in,
                              void* d_out, int out_size)
{
    const float* wq     = (const float*)d_in[0];
    const float* wk     = (const float*)d_in[1];
    const float* wv     = (const float*)d_in[2];
    const float* wo     = (const float*)d_in[3];
    const float* w1     = (const float*)d_in[4];
    const float* w2     = (const float*)d_in[5];
    const float* embed  = (const float*)d_in[6];
    const float* biases = (const float*)d_in[7];

    long n[7];
    for (int t = 0; t < 7; t++) n[t] = (long)in_sizes[t];

    // Unit size: 2048 float4 (32KB) = one MLP8 batch per thread; grow if NU > MAXU.
    int unit_f4 = 2048;
    int ub[8];
    for (;;) {
        ub[0] = 0;
        for (int t = 0; t < 7; t++) {
            long n4e = n[t] >> 2;
            long nu  = (n4e + unit_f4 - 1) / unit_f4;
            ub[t + 1] = ub[t] + (int)nu;
        }
        if (ub[7] <= MAXU) break;
        unit_f4 <<= 1;
    }

    wr_fused_kernel<<<NBLK, NT>>>(wq, wk, wv, wo, w1, w2, embed, biases,
                                  n[0], n[1], n[2], n[3], n[4], n[5], n[6],
                                  ub[1], ub[2], ub[3], ub[4], ub[5], ub[6], ub[7],
                                  unit_f4, (float*)d_out);
}

// round 17
// speedup vs baseline: 1.1714x; 1.1714x over previous
#include <cuda_runtime.h>
#include <cuda_bf16.h>

#define NT   256
#define NBLK 740      // exactly one wave: 5 CTAs/SM x 148 SMs
#define MAXU 16384    // max work units (unit size auto-scales if exceeded)

// Scratch. Unit partials: every slot in [0, NU) written every launch.
// Counters reset by the last block -> graph-replay deterministic.
__device__ float g_unit_partials[MAXU];
__device__ float g_rowsums[128];
__device__ int   g_ticket = 0;
__device__ int   g_count  = 0;

__device__ __forceinline__ float block_reduce(float v, float* sdata) {
    int tid = threadIdx.x;
    #pragma unroll
    for (int off = 16; off > 0; off >>= 1)
        v += __shfl_down_sync(0xFFFFFFFFu, v, off);
    if ((tid & 31) == 0) sdata[tid >> 5] = v;
    __syncthreads();
    float r = 0.0f;
    if (tid < (NT / 32)) r = sdata[tid];
    if (tid < 32) {
        #pragma unroll
        for (int off = (NT / 64); off > 0; off >>= 1)
            r += __shfl_down_sync(0xFFFFFFFFu, r, off);
    }
    return r;  // valid in tid 0
}

__device__ __forceinline__ float sq4(float4 v, float s) {
    s = fmaf(v.x, v.x, s); s = fmaf(v.y, v.y, s);
    s = fmaf(v.z, v.z, s); s = fmaf(v.w, v.w, s);
    return s;
}

// Unit boundaries: tensor t owns units [ub[t], ub[t+1]); NU = ub[7].
__global__ __launch_bounds__(NT, 5)
void wr_fused_kernel(const float* __restrict__ wq, const float* __restrict__ wk,
                     const float* __restrict__ wv, const float* __restrict__ wo,
                     const float* __restrict__ w1, const float* __restrict__ w2,
                     const float* __restrict__ embed, const float* __restrict__ biases,
                     long n0, long n1, long n2, long n3, long n4, long n5, long n6,
                     int u1, int u2, int u3, int u4, int u5, int u6, int u7,
                     int unit_f4,
                     float* __restrict__ out)
{
    __shared__ float sdata[NT / 32];
    __shared__ int   s_u;
    const float* ptrs[7] = {wq, wk, wv, wo, w1, w2, embed};
    const long ns[7]     = {n0, n1, n2, n3, n4, n5, n6};
    const int  ub[8]     = {0, u1, u2, u3, u4, u5, u6, u7};
    const int  NU        = u7;
    const int  tid       = threadIdx.x;
    const int  bid       = blockIdx.x;

    // ---- dynamic work-stealing over fixed 64KB units ----
    if (tid == 0) s_u = atomicAdd(&g_ticket, 1);
    __syncthreads();
    int u = s_u;
    while (u < NU) {
        int t = 0;
        #pragma unroll
        for (int k = 1; k < 7; k++) if (u >= ub[k]) t = k;
        const float4* __restrict__ p = (const float4*)ptrs[t];
        const long n4e = ns[t] >> 2;
        const long lo  = (long)(u - ub[t]) * unit_f4;
        long hi = lo + unit_f4; if (hi > n4e) hi = n4e;

        float s0 = 0.f, s1 = 0.f, s2 = 0.f, s3 = 0.f;
        float s4 = 0.f, s5 = 0.f, s6 = 0.f, s7 = 0.f;
        long i = lo + tid;
        for (; i + 7 * NT < hi; i += 8 * NT) {
            float4 a = __ldcs(p + i);
            float4 b = __ldcs(p + i + NT);
            float4 c = __ldcs(p + i + 2 * NT);
            float4 d = __ldcs(p + i + 3 * NT);
            float4 e = __ldcs(p + i + 4 * NT);
            float4 f = __ldcs(p + i + 5 * NT);
            float4 g = __ldcs(p + i + 6 * NT);
            float4 h = __ldcs(p + i + 7 * NT);
            s0 = sq4(a, s0); s1 = sq4(b, s1); s2 = sq4(c, s2); s3 = sq4(d, s3);
            s4 = sq4(e, s4); s5 = sq4(f, s5); s6 = sq4(g, s6); s7 = sq4(h, s7);
        }
        for (; i < hi; i += NT) s0 = sq4(__ldcs(p + i), s0);

        __syncthreads();  // all threads consumed s_u
        if (tid == 0) s_u = atomicAdd(&g_ticket, 1);  // latency overlaps reduce

        float s = ((s0 + s1) + (s2 + s3)) + ((s4 + s5) + (s6 + s7));
        float r = block_reduce(s, sdata);
        if (tid == 0) g_unit_partials[u] = r;
        __syncthreads();
        u = s_u;
    }

    // Bias rows: blocks 0..127 each do one 8KB row
    if (bid < 128) {
        const float4* __restrict__ pb = (const float4*)(biases) + (long)bid * 512;
        float sb = 0.0f;
        for (int j = tid; j < 512; j += NT) sb = sq4(__ldcs(pb + j), sb);
        float rb = block_reduce(sb, sdata);
        if (tid == 0) g_rowsums[bid] = rb;
        __syncthreads();
    }

    // ---- last-block finalize (unit partials are L2-hot) ----
    __shared__ bool is_last;
    __threadfence();
    if (tid == 0) {
        int c = atomicAdd(&g_count, 1);
        is_last = (c == (int)gridDim.x - 1);
    }
    __syncthreads();
    if (!is_last) return;
    __threadfence();  // acquire side

    __shared__ float s_total;
    if (tid == 0) s_total = 0.0f;
    __syncthreads();

    #pragma unroll 1
    for (int tt = 0; tt < 7; tt++) {
        float sv = 0.0f;
        #pragma unroll 4
        for (int j = ub[tt] + tid; j < ub[tt + 1]; j += NT) sv += g_unit_partials[j];
        // scalar tail (n % 4): empty for these shapes
        if (tid == 0) {
            const float* pf = ptrs[tt];
            const long n = ns[tt];
            for (long j = (n >> 2) << 2; j < n; j++) sv = fmaf(pf[j], pf[j], sv);
        }
        float rv = block_reduce(sv, sdata);
        if (tid == 0) s_total += sqrtf(rv);
        __syncthreads();
    }

    float s2v = 0.0f;
    for (int j = tid; j < 128; j += NT) s2v += sqrtf(g_rowsums[j]);
    float rb2 = block_reduce(s2v, sdata);
    if (tid == 0) {
        out[0] = 0.0001f * ((s_total + rb2) / 135.0f);  // 7 mats + 128 rows
        g_ticket = 0;  // reset for next graph replay
        g_count  = 0;
    }
}

extern "C" void kernel_launch(void* const* d_in, const int* in_sizes, int n_in,
                              void* d_out, int out_size)
{
    const float* wq     = (const float*)d_in[0];
    const float* wk     = (const float*)d_in[1];
    const float* wv     = (const float*)d_in[2];
    const float* wo     = (const float*)d_in[3];
    const float* w1     = (const float*)d_in[4];
    const float* w2     = (const float*)d_in[5];
    const float* embed  = (const float*)d_in[6];
    const float* biases = (const float*)d_in[7];

    long n[7];
    for (int t = 0; t < 7; t++) n[t] = (long)in_sizes[t];

    // Unit size: 4096 float4 (64KB) = two MLP8 batches per thread; grow if NU > MAXU.
    int unit_f4 = 4096;
    int ub[8];
    for (;;) {
        ub[0] = 0;
        for (int t = 0; t < 7; t++) {
            long n4e = n[t] >> 2;
            long nu  = (n4e + unit_f4 - 1) / unit_f4;
            ub[t + 1] = ub[t] + (int)nu;
        }
        if (ub[7] <= MAXU) break;
        unit_f4 <<= 1;
    }

    wr_fused_kernel<<<NBLK, NT>>>(wq, wk, wv, wo, w1, w2, embed, biases,
                                  n[0], n[1], n[2], n[3], n[4], n[5], n[6],
                                  ub[1], ub[2], ub[3], ub[4], ub[5], ub[6], ub[7],
                                  unit_f4, (float*)d_out);
}